// round 6
// baseline (speedup 1.0000x reference)
#include <cuda_runtime.h>
#include <math.h>
#include <cstdint>

#define NB 4
#define NL 1024
#define ND 1024
#define NH 16
#define NHD 64
#define NBH (NB*NH)

// ---------------- scratch (device globals) ----------------
__device__ __align__(16) float g_qcat[NBH*NL*192];     // [bh][l][pq|hq|vq]
__device__ __align__(16) float g_kcat[NBH*NL*192];     // [bh][l][k|cf|bf]
__device__ __align__(16) float g_v [NBH*NL*NHD];
__device__ __align__(16) float g_vt[NBH*NL*NHD];
__device__ __align__(16) float g_ctx[NB*NL*ND];
__device__ __align__(16) float g_wt[6u*1024u*1024u];   // transposed (+tf32-rounded) weights
__device__ __align__(16) float g_bcat[3072];
__device__ __align__(16) float g_pmax[NBH*NL*8];
__device__ __align__(16) float g_psum[NBH*NL*8];
__device__ __align__(16) float g_rowm[NBH*NL];
__device__ __align__(16) float g_rowi[NBH*NL];

// ---------------- helpers ----------------
__device__ __forceinline__ float rnd_tf32(float x) {
    uint32_t u;
    asm("cvt.rna.tf32.f32 %0, %1;" : "=r"(u) : "f"(x));
    return __uint_as_float(u);
}
__device__ __forceinline__ uint32_t rnd_tf32_u(uint32_t x) {
    uint32_t u;
    asm("cvt.rna.tf32.f32 %0, %1;" : "=r"(u) : "f"(__uint_as_float(x)));
    return u;
}
__device__ __forceinline__ void cpa16(uint32_t s, const void* g) {
    asm volatile("cp.async.cg.shared.global [%0], [%1], 16;" :: "r"(s), "l"(g) : "memory");
}
__device__ __forceinline__ uint32_t s2u(const void* p) {
    return (uint32_t)__cvta_generic_to_shared(p);
}
__device__ __forceinline__ void ldsm4(uint32_t (&r)[4], uint32_t a) {
    asm volatile("ldmatrix.sync.aligned.m8n8.x4.shared.b16 {%0,%1,%2,%3}, [%4];"
        : "=r"(r[0]), "=r"(r[1]), "=r"(r[2]), "=r"(r[3]) : "r"(a));
}
__device__ __forceinline__ void ldsm2(uint32_t (&r)[2], uint32_t a) {
    asm volatile("ldmatrix.sync.aligned.m8n8.x2.shared.b16 {%0,%1}, [%2];"
        : "=r"(r[0]), "=r"(r[1]) : "r"(a));
}

#define PITCH 36   // floats; rows stride 144B -> 16B aligned, ldmatrix conflict-free
#define NSTG 3     // pipeline stages

// warp-level tf32 mma over one BK=32 stage; fragments via ldmatrix.
template<int MSUB, int NSUB, bool RA>
__device__ __forceinline__ void warp_mma(
    const float* __restrict__ As, const float* __restrict__ Bs,
    int mrow0, int ncol0, float (&acc)[MSUB][NSUB][4],
    int rA, int cA, int rB, int cB)
{
#pragma unroll
    for (int k8 = 0; k8 < 4; k8++) {
        uint32_t a[MSUB][4];
#pragma unroll
        for (int mi = 0; mi < MSUB; mi++) {
            ldsm4(a[mi], s2u(As + (mrow0 + mi*16 + rA)*PITCH + k8*8 + cA));
            if (RA) {
#pragma unroll
                for (int q = 0; q < 4; q++) a[mi][q] = rnd_tf32_u(a[mi][q]);
            }
        }
        uint32_t b[NSUB][2];
#pragma unroll
        for (int ni = 0; ni < NSUB; ni++)
            ldsm2(b[ni], s2u(Bs + (ncol0 + ni*8 + rB)*PITCH + k8*8 + cB));
#pragma unroll
        for (int mi = 0; mi < MSUB; mi++)
#pragma unroll
            for (int ni = 0; ni < NSUB; ni++) {
                asm volatile(
                    "mma.sync.aligned.m16n8k8.row.col.f32.tf32.tf32.f32 "
                    "{%0,%1,%2,%3}, {%4,%5,%6,%7}, {%8,%9}, {%0,%1,%2,%3};"
                    : "+f"(acc[mi][ni][0]), "+f"(acc[mi][ni][1]),
                      "+f"(acc[mi][ni][2]), "+f"(acc[mi][ni][3])
                    : "r"(a[mi][0]), "r"(a[mi][1]), "r"(a[mi][2]), "r"(a[mi][3]),
                      "r"(b[ni][0]), "r"(b[ni][1]));
            }
    }
}

// output layouts
#define LAY_FLAT 0
#define LAY_HEAD 1
#define LAY_QCAT 2
#define LAY_KCAT 3

template<int LAYOUT>
__device__ __forceinline__ float* out_addr(float* C, int mrow, int ncol) {
    if (LAYOUT == LAY_FLAT) return C + (size_t)mrow*1024 + ncol;
    int b = mrow >> 10, l = mrow & 1023;
    if (LAYOUT == LAY_HEAD) {
        int h = ncol >> 6, hd = ncol & 63;
        return C + ((size_t)((b*16 + h)*1024 + l))*64 + hd;
    }
    if (LAYOUT == LAY_QCAT) {
        int seg = ncol >> 10, nn = ncol & 1023;
        int h = nn >> 6, hd = nn & 63;
        return C + ((size_t)((b*16 + h)*1024 + l))*192 + seg*64 + hd;
    }
    int h = ncol >> 6, hd = ncol & 63;
    return C + ((size_t)((b*16 + h)*1024 + l))*192 + hd;
}

// ============================================================
// mma_gemm: C = A[4096x1024] @ BT^T + bias, BT=[N,K]
// 128x128 block, BK=32, 8 warps, 3-stage cp.async pipeline
// ============================================================
template<int LAYOUT, bool ROUND, bool RA>
__global__ void __launch_bounds__(256, 2) mma_gemm(
    const float* __restrict__ A, const float* __restrict__ BT,
    const float* __restrict__ bias, float* __restrict__ C)
{
    extern __shared__ float sm[];
    float* Asb[NSTG]; float* Bsb[NSTG];
#pragma unroll
    for (int s = 0; s < NSTG; s++) {
        Asb[s] = sm + s*2*128*PITCH;
        Bsb[s] = sm + s*2*128*PITCH + 128*PITCH;
    }
    const int tid = threadIdx.x, lane = tid & 31, wid = tid >> 5;
    const int wm = wid & 1, wn = wid >> 1;
    const int g = lane >> 2, t = lane & 3;
    const int rA = ((lane >> 3) & 1)*8 + (lane & 7), cA = (lane >> 4)*4;
    const int rB = lane & 7, cB = ((lane >> 3) & 1)*4;
    const int m0 = blockIdx.y * 128, n0 = blockIdx.x * 128;

    float acc[4][4][4] = {};

#define LOAD_STAGE(i) do {                                                 \
        if ((i) < 32) {                                                    \
            int k0 = (i) * 32; int ss = (i) % NSTG;                        \
            _Pragma("unroll")                                              \
            for (int it = 0; it < 4; it++) {                               \
                int j = it*256 + tid;                                      \
                int r = j >> 3, c = j & 7;                                 \
                cpa16(s2u(Asb[ss] + r*PITCH + c*4), A  + (size_t)(m0+r)*1024 + k0 + c*4); \
                cpa16(s2u(Bsb[ss] + r*PITCH + c*4), BT + (size_t)(n0+r)*1024 + k0 + c*4); \
            }                                                              \
        }                                                                  \
        asm volatile("cp.async.commit_group;" ::: "memory");               \
    } while (0)

    LOAD_STAGE(0);
    LOAD_STAGE(1);
    for (int i = 0; i < 32; i++) {
        int s = i % NSTG;
        asm volatile("cp.async.wait_group 1;" ::: "memory");
        __syncthreads();
        LOAD_STAGE(i + 2);
        warp_mma<4,4,RA>(Asb[s], Bsb[s], wm*64, wn*32, acc, rA, cA, rB, cB);
    }
#undef LOAD_STAGE

#pragma unroll
    for (int mi = 0; mi < 4; mi++)
#pragma unroll
        for (int ni = 0; ni < 4; ni++) {
            int mrow = m0 + wm*64 + mi*16 + g;
            int ncol = n0 + wn*32 + ni*8 + t*2;
            float b0 = bias[ncol], b1 = bias[ncol+1];
            float v00 = acc[mi][ni][0] + b0, v01 = acc[mi][ni][1] + b1;
            float v10 = acc[mi][ni][2] + b0, v11 = acc[mi][ni][3] + b1;
            if (ROUND) { v00 = rnd_tf32(v00); v01 = rnd_tf32(v01);
                         v10 = rnd_tf32(v10); v11 = rnd_tf32(v11); }
            *(float2*)out_addr<LAYOUT>(C, mrow,     ncol) = make_float2(v00, v01);
            *(float2*)out_addr<LAYOUT>(C, mrow + 8, ncol) = make_float2(v10, v11);
        }
}

// ============================================================
// mma_score: raw scaled scores + per-tile row partials, K=192
// ============================================================
__global__ void __launch_bounds__(256, 2) mma_score(
    const float* __restrict__ qcat, const float* __restrict__ kcat,
    float* __restrict__ attn, float* __restrict__ pmax, float* __restrict__ psum)
{
    extern __shared__ float sm[];
    float* Asb[NSTG]; float* Bsb[NSTG];
#pragma unroll
    for (int s = 0; s < NSTG; s++) {
        Asb[s] = sm + s*2*128*PITCH;
        Bsb[s] = sm + s*2*128*PITCH + 128*PITCH;
    }
    const int tid = threadIdx.x, lane = tid & 31, wid = tid >> 5;
    const int wm = wid & 1, wn = wid >> 1;
    const int g = lane >> 2, t = lane & 3;
    const int rA = ((lane >> 3) & 1)*8 + (lane & 7), cA = (lane >> 4)*4;
    const int rB = lane & 7, cB = ((lane >> 3) & 1)*4;
    const int bh = blockIdx.z;
    const int q0 = blockIdx.y * 128, n0 = blockIdx.x * 128;
    const float* Ab = qcat + (size_t)bh*NL*192 + (size_t)q0*192;
    const float* Bb = kcat + (size_t)bh*NL*192 + (size_t)n0*192;

    float acc[4][4][4] = {};

#define LOAD_STAGE_S(i) do {                                               \
        if ((i) < 6) {                                                     \
            int k0 = (i) * 32; int ss = (i) % NSTG;                        \
            _Pragma("unroll")                                              \
            for (int it = 0; it < 4; it++) {                               \
                int j = it*256 + tid;                                      \
                int r = j >> 3, c = j & 7;                                 \
                cpa16(s2u(Asb[ss] + r*PITCH + c*4), Ab + (size_t)r*192 + k0 + c*4); \
                cpa16(s2u(Bsb[ss] + r*PITCH + c*4), Bb + (size_t)r*192 + k0 + c*4); \
            }                                                              \
        }                                                                  \
        asm volatile("cp.async.commit_group;" ::: "memory");               \
    } while (0)

    LOAD_STAGE_S(0);
    LOAD_STAGE_S(1);
    for (int i = 0; i < 6; i++) {
        int s = i % NSTG;
        asm volatile("cp.async.wait_group 1;" ::: "memory");
        __syncthreads();
        LOAD_STAGE_S(i + 2);
        warp_mma<4,4,false>(Asb[s], Bsb[s], wm*64, wn*32, acc, rA, cA, rB, cB);
    }
#undef LOAD_STAGE_S

    const float sc = 1.0f / 24.0f;
#pragma unroll
    for (int mi = 0; mi < 4; mi++)
#pragma unroll
        for (int ni = 0; ni < 4; ni++) {
            int mrow = q0 + wm*64 + mi*16 + g;
            int ncol = n0 + wn*32 + ni*8 + t*2;
            float* d0 = attn + ((size_t)bh*NL + mrow)*NL + ncol;
            float* d1 = attn + ((size_t)bh*NL + mrow + 8)*NL + ncol;
            *(float2*)d0 = make_float2(acc[mi][ni][0]*sc, acc[mi][ni][1]*sc);
            *(float2*)d1 = make_float2(acc[mi][ni][2]*sc, acc[mi][ni][3]*sc);
        }

    __syncthreads();
    float* pm = sm;          // [128][4]
    float* ps = sm + 512;    // [128][4]
#pragma unroll
    for (int mi = 0; mi < 4; mi++)
#pragma unroll
        for (int half = 0; half < 2; half++) {
            float v[8];
#pragma unroll
            for (int ni = 0; ni < 4; ni++) {
                v[ni*2+0] = acc[mi][ni][half*2+0] * sc;
                v[ni*2+1] = acc[mi][ni][half*2+1] * sc;
            }
            float mx = v[0];
#pragma unroll
            for (int q = 1; q < 8; q++) mx = fmaxf(mx, v[q]);
            mx = fmaxf(mx, __shfl_xor_sync(0xffffffffu, mx, 1));
            mx = fmaxf(mx, __shfl_xor_sync(0xffffffffu, mx, 2));
            float se = 0.f;
#pragma unroll
            for (int q = 0; q < 8; q++) se += __expf(v[q] - mx);
            se += __shfl_xor_sync(0xffffffffu, se, 1);
            se += __shfl_xor_sync(0xffffffffu, se, 2);
            if (t == 0) {
                int lr = wm*64 + mi*16 + half*8 + g;
                pm[lr*4 + wn] = mx;
                ps[lr*4 + wn] = se;
            }
        }
    __syncthreads();
    if (tid < 128) {
        int lr = tid;
        float M = pm[lr*4];
#pragma unroll
        for (int q = 1; q < 4; q++) M = fmaxf(M, pm[lr*4+q]);
        float S = 0.f;
#pragma unroll
        for (int q = 0; q < 4; q++) S += ps[lr*4+q] * __expf(pm[lr*4+q] - M);
        size_t row = (size_t)bh*NL + q0 + lr;
        pmax[row*8 + blockIdx.x] = M;
        psum[row*8 + blockIdx.x] = S;
    }
}

// ============================================================
// combine_rows
// ============================================================
__global__ void __launch_bounds__(256) combine_rows(
    const float* __restrict__ pmax, const float* __restrict__ psum,
    float* __restrict__ rowm, float* __restrict__ rowi)
{
    int row = blockIdx.x * 256 + threadIdx.x;
    const float* pmr = pmax + (size_t)row*8;
    const float* psr = psum + (size_t)row*8;
    float M = pmr[0];
#pragma unroll
    for (int q = 1; q < 8; q++) M = fmaxf(M, pmr[q]);
    float S = 0.f;
#pragma unroll
    for (int q = 0; q < 8; q++) S += psr[q] * __expf(pmr[q] - M);
    rowm[row] = M;
    rowi[row] = 1.0f / S;
}

// ============================================================
// mma_ctx: fused softmax-apply + PV gemm (in-place attn normalize)
// ============================================================
__global__ void __launch_bounds__(256, 2) mma_ctx(
    float* __restrict__ attn, const float* __restrict__ vt,
    const float* __restrict__ rowm, const float* __restrict__ rowi,
    float* __restrict__ ctx)
{
    extern __shared__ float sm[];
    float* Asb[NSTG]; float* Bsb[NSTG];
#pragma unroll
    for (int s = 0; s < NSTG; s++) {
        Asb[s] = sm + s*(128+64)*PITCH;
        Bsb[s] = sm + s*(128+64)*PITCH + 128*PITCH;
    }
    float* rowM = sm + NSTG*(128+64)*PITCH;
    float* rowI = rowM + 128;
    const int tid = threadIdx.x, lane = tid & 31, wid = tid >> 5;
    const int wm = wid & 1, wn = wid >> 1;
    const int g = lane >> 2, t = lane & 3;
    const int rA = ((lane >> 3) & 1)*8 + (lane & 7), cA = (lane >> 4)*4;
    const int rB = lane & 7, cB = ((lane >> 3) & 1)*4;
    const int bh = blockIdx.y, q0 = blockIdx.x * 128;
    float* Ab = attn + (size_t)bh*NL*NL + (size_t)q0*NL;
    const float* Bb = vt + (size_t)bh*64*NL;

    if (tid < 128) {
        rowM[tid] = rowm[(size_t)bh*NL + q0 + tid];
        rowI[tid] = rowi[(size_t)bh*NL + q0 + tid];
    }

    float acc[4][2][4] = {};

#define LOAD_STAGE_C(i) do {                                               \
        if ((i) < 32) {                                                    \
            int k0 = (i) * 32; int ss = (i) % NSTG;                        \
            _Pragma("unroll")                                              \
            for (int it = 0; it < 4; it++) {                               \
                int j = it*256 + tid;                                      \
                int r = j >> 3, c = j & 7;                                 \
                cpa16(s2u(Asb[ss] + r*PITCH + c*4), Ab + (size_t)r*NL + k0 + c*4); \
            }                                                              \
            _Pragma("unroll")                                              \
            for (int it = 0; it < 2; it++) {                               \
                int j = it*256 + tid;                                      \
                int r = j >> 3, c = j & 7;                                 \
                cpa16(s2u(Bsb[ss] + r*PITCH + c*4), Bb + (size_t)r*NL + k0 + c*4); \
            }                                                              \
        }                                                                  \
        asm volatile("cp.async.commit_group;" ::: "memory");               \
    } while (0)

    LOAD_STAGE_C(0);
    LOAD_STAGE_C(1);
    for (int i = 0; i < 32; i++) {
        int s = i % NSTG;
        asm volatile("cp.async.wait_group 1;" ::: "memory");
        __syncthreads();
        LOAD_STAGE_C(i + 2);
        // softmax transform on this 128x32 score chunk, in smem; write attn back
        {
            int k0 = i * 32;
#pragma unroll
            for (int it = 0; it < 4; it++) {
                int j = it*256 + tid;
                int r = j >> 3, c4 = j & 7;
                float4* ap = (float4*)(Asb[s] + r*PITCH + c4*4);
                float4 v = *ap;
                float M = rowM[r], I = rowI[r];
                v.x = rnd_tf32(__expf(v.x - M) * I);
                v.y = rnd_tf32(__expf(v.y - M) * I);
                v.z = rnd_tf32(__expf(v.z - M) * I);
                v.w = rnd_tf32(__expf(v.w - M) * I);
                *ap = v;
                *(float4*)(Ab + (size_t)r*NL + k0 + c4*4) = v;
            }
        }
        __syncthreads();
        warp_mma<4,2,false>(Asb[s], Bsb[s], wm*64, wn*16, acc, rA, cA, rB, cB);
    }
#undef LOAD_STAGE_C

    const int b = bh >> 4, hh = bh & 15;
#pragma unroll
    for (int mi = 0; mi < 4; mi++)
#pragma unroll
        for (int ni = 0; ni < 2; ni++) {
            int mrow = q0 + wm*64 + mi*16 + g;
            int ncol = wn*16 + ni*8 + t*2;
            float v00 = rnd_tf32(acc[mi][ni][0]), v01 = rnd_tf32(acc[mi][ni][1]);
            float v10 = rnd_tf32(acc[mi][ni][2]), v11 = rnd_tf32(acc[mi][ni][3]);
            *(float2*)(ctx + ((size_t)(b*1024 + mrow))*1024 + hh*64 + ncol) = make_float2(v00, v01);
            *(float2*)(ctx + ((size_t)(b*1024 + mrow + 8))*1024 + hh*64 + ncol) = make_float2(v10, v11);
        }
}

// ============================================================
// batched 1024x1024 transpose (+ tf32 round), 6 matrices in one launch
// ============================================================
struct TP6 { const float* src[6]; float* dst[6]; };

__global__ void __launch_bounds__(256) transpose6(TP6 p)
{
    __shared__ float tbuf[32][33];
    const int z = blockIdx.z;
    const float* src = p.src[z];
    float* dst = p.dst[z];
    const int bx = blockIdx.x * 32, by = blockIdx.y * 32;
    const int x = threadIdx.x, y0 = threadIdx.y;
#pragma unroll
    for (int dy = 0; dy < 32; dy += 8)
        tbuf[y0+dy][x] = src[(size_t)(by + y0 + dy)*1024 + bx + x];
    __syncthreads();
#pragma unroll
    for (int dy = 0; dy < 32; dy += 8)
        dst[(size_t)(bx + y0 + dy)*1024 + by + x] = rnd_tf32(tbuf[x][y0+dy]);
}

// v transpose: vt[bh][hd][l] = v[bh][l][hd]
__global__ void __launch_bounds__(256) transpose_v(
    const float* __restrict__ src, float* __restrict__ dst)
{
    __shared__ float tbuf[32][33];
    const int bx = blockIdx.x * 32, by = blockIdx.y * 32;
    const size_t base = (size_t)blockIdx.z * NL * 64;
    const int x = threadIdx.x, y0 = threadIdx.y;
#pragma unroll
    for (int dy = 0; dy < 32; dy += 8)
        tbuf[y0+dy][x] = src[base + (size_t)(by + y0 + dy)*64 + bx + x];
    __syncthreads();
#pragma unroll
    for (int dy = 0; dy < 32; dy += 8)
        dst[base + (size_t)(bx + y0 + dy)*NL + by + x] = rnd_tf32(tbuf[x][y0+dy]);
}

__global__ void __launch_bounds__(256) concat_bias(
    const float* __restrict__ a, const float* __restrict__ b,
    const float* __restrict__ c, float* __restrict__ o)
{
    int i = blockIdx.x * 256 + threadIdx.x;
    o[i] = (i < 1024) ? a[i] : (i < 2048) ? b[i - 1024] : c[i - 2048];
}

// ============================================================
// chord/bass features -> Kcat segments 1,2 (replicated over b)
// ============================================================
__global__ __launch_bounds__(256) void chordfeat(
    const int* __restrict__ pc, const int* __restrict__ bon,
    const float* __restrict__ Wc, const float* __restrict__ bc,
    const float* __restrict__ Wb, const float* __restrict__ bb,
    float* __restrict__ kcat)
{
    int idx = blockIdx.x * 256 + threadIdx.x;
    int l = idx >> 10, n = idx & 1023;
    float sc = bc[n], sb = bb[n];
#pragma unroll
    for (int p = 0; p < 12; p++) {
        sc += (float)pc[l*12 + p] * Wc[p*1024 + n];
        sb += (float)bon[l*12 + p] * Wb[p*1024 + n];
    }
    sc = rnd_tf32(sc); sb = rnd_tf32(sb);
    int h = n >> 6, hd = n & 63;
#pragma unroll
    for (int b = 0; b < 4; b++) {
        size_t row = ((size_t)((b*16 + h)*1024 + l))*192;
        kcat[row + 64 + hd]  = sc;
        kcat[row + 128 + hd] = sb;
    }
}

// ============================================================
// launch
// ============================================================
extern "C" void kernel_launch(void* const* d_in, const int* in_sizes, int n_in,
                              void* d_out, int out_size)
{
    const float* query = (const float*)d_in[0];
    const float* key   = (const float*)d_in[1];
    const float* value = (const float*)d_in[2];
    const int*   pc    = (const int*)d_in[3];
    const int*   bon   = (const int*)d_in[4];
    const float* Wpq = (const float*)d_in[5],  *bpq = (const float*)d_in[6];
    const float* Whq = (const float*)d_in[7],  *bhq = (const float*)d_in[8];
    const float* Wvq = (const float*)d_in[9],  *bvq = (const float*)d_in[10];
    const float* Wk  = (const float*)d_in[11], *bk  = (const float*)d_in[12];
    const float* Wv  = (const float*)d_in[13], *bv  = (const float*)d_in[14];
    const float* Wc  = (const float*)d_in[15], *bc  = (const float*)d_in[16];
    const float* Wb  = (const float*)d_in[17], *bb  = (const float*)d_in[18];
    const float* Wo  = (const float*)d_in[19], *bo  = (const float*)d_in[20];

    float *qcat_p, *kcat_p, *v_p, *vt_p, *ctx_p, *wt_p, *bcat_p;
    float *pmax_p, *psum_p, *rowm_p, *rowi_p;
    cudaGetSymbolAddress((void**)&qcat_p, g_qcat);
    cudaGetSymbolAddress((void**)&kcat_p, g_kcat);
    cudaGetSymbolAddress((void**)&v_p,    g_v);
    cudaGetSymbolAddress((void**)&vt_p,   g_vt);
    cudaGetSymbolAddress((void**)&ctx_p,  g_ctx);
    cudaGetSymbolAddress((void**)&wt_p,   g_wt);
    cudaGetSymbolAddress((void**)&bcat_p, g_bcat);
    cudaGetSymbolAddress((void**)&pmax_p, g_pmax);
    cudaGetSymbolAddress((void**)&psum_p, g_psum);
    cudaGetSymbolAddress((void**)&rowm_p, g_rowm);
    cudaGetSymbolAddress((void**)&rowi_p, g_rowi);

    float* WqcatT = wt_p;                       // [3072 x 1024]
    float* WkT    = wt_p + 3u*1024u*1024u;
    float* WvT    = wt_p + 4u*1024u*1024u;
    float* WoT    = wt_p + 5u*1024u*1024u;

    float* out  = (float*)d_out;
    float* attn = out + (size_t)NB * NL * ND;

    const int SM_BIG = NSTG * 2 * 128 * PITCH * 4;                  // 110592
    const int SM_CTX = (NSTG * (128+64) * PITCH + 256) * 4;         // 83968
    cudaFuncSetAttribute(mma_gemm<LAY_QCAT,true,true>,  cudaFuncAttributeMaxDynamicSharedMemorySize, SM_BIG);
    cudaFuncSetAttribute(mma_gemm<LAY_KCAT,true,true>,  cudaFuncAttributeMaxDynamicSharedMemorySize, SM_BIG);
    cudaFuncSetAttribute(mma_gemm<LAY_HEAD,true,true>,  cudaFuncAttributeMaxDynamicSharedMemorySize, SM_BIG);
    cudaFuncSetAttribute(mma_gemm<LAY_FLAT,false,false>,cudaFuncAttributeMaxDynamicSharedMemorySize, SM_BIG);
    cudaFuncSetAttribute(mma_score,                     cudaFuncAttributeMaxDynamicSharedMemorySize, SM_BIG);
    cudaFuncSetAttribute(mma_ctx,                       cudaFuncAttributeMaxDynamicSharedMemorySize, SM_CTX);

    // transpose + round all six 1024x1024 weights in one launch
    TP6 tp;
    tp.src[0] = Wpq; tp.dst[0] = WqcatT + 0u*1024u*1024u;
    tp.src[1] = Whq; tp.dst[1] = WqcatT + 1u*1024u*1024u;
    tp.src[2] = Wvq; tp.dst[2] = WqcatT + 2u*1024u*1024u;
    tp.src[3] = Wk;  tp.dst[3] = WkT;
    tp.src[4] = Wv;  tp.dst[4] = WvT;
    tp.src[5] = Wo;  tp.dst[5] = WoT;
    dim3 tb(32, 8);
    transpose6<<<dim3(32, 32, 6), tb>>>(tp);
    concat_bias<<<12, 256>>>(bpq, bhq, bvq, bcat_p);

    // projections (A-fragment tf32 rounding fused)
    mma_gemm<LAY_QCAT,true,true><<<dim3(24, 32), 256, SM_BIG>>>(query, WqcatT, bcat_p, qcat_p);
    mma_gemm<LAY_KCAT,true,true><<<dim3(8, 32),  256, SM_BIG>>>(key,   WkT, bk, kcat_p);
    mma_gemm<LAY_HEAD,true,true><<<dim3(8, 32),  256, SM_BIG>>>(value, WvT, bv, v_p);

    transpose_v<<<dim3(2, 32, NBH), tb>>>(v_p, vt_p);
    chordfeat<<<4096, 256>>>(pc, bon, Wc, bc, Wb, bb, kcat_p);

    mma_score<<<dim3(8, 8, NBH), 256, SM_BIG>>>(qcat_p, kcat_p, attn, pmax_p, psum_p);
    combine_rows<<<NBH*NL/256, 256>>>(pmax_p, psum_p, rowm_p, rowi_p);
    mma_ctx<<<dim3(8, NBH), 256, SM_CTX>>>(attn, vt_p, rowm_p, rowi_p, ctx_p);
    mma_gemm<LAY_FLAT,false,false><<<dim3(8, 32), 256, SM_BIG>>>(ctx_p, WoT, bo, out);
}

// round 7
// speedup vs baseline: 1.0463x; 1.0463x over previous
#include <cuda_runtime.h>
#include <math.h>
#include <cstdint>

#define NB 4
#define NL 1024
#define ND 1024
#define NH 16
#define NHD 64
#define NBH (NB*NH)

// ---------------- scratch (device globals) ----------------
__device__ __align__(16) float g_qcat[NBH*NL*192];     // [bh][l][pq|hq|vq]
__device__ __align__(16) float g_kcat[NBH*NL*192];     // [bh][l][k|cf|bf]
__device__ __align__(16) float g_v [NBH*NL*NHD];
__device__ __align__(16) float g_vt[NBH*NL*NHD];
__device__ __align__(16) float g_ctx[NB*NL*ND];
__device__ __align__(16) float g_wt[6u*1024u*1024u];   // transposed (+tf32-rounded) weights
__device__ __align__(16) float g_qr[NB*NL*ND];         // tf32-rounded inputs
__device__ __align__(16) float g_kr[NB*NL*ND];
__device__ __align__(16) float g_vr[NB*NL*ND];
__device__ __align__(16) float g_bcat[3072];
__device__ __align__(16) float g_pmax[NBH*NL*8];
__device__ __align__(16) float g_psum[NBH*NL*8];
__device__ __align__(16) float g_rowm[NBH*NL];
__device__ __align__(16) float g_rowi[NBH*NL];

// ---------------- helpers ----------------
__device__ __forceinline__ float rnd_tf32(float x) {
    uint32_t u;
    asm("cvt.rna.tf32.f32 %0, %1;" : "=r"(u) : "f"(x));
    return __uint_as_float(u);
}
__device__ __forceinline__ void cpa16(uint32_t s, const void* g) {
    asm volatile("cp.async.cg.shared.global [%0], [%1], 16;" :: "r"(s), "l"(g) : "memory");
}
__device__ __forceinline__ uint32_t s2u(const void* p) {
    return (uint32_t)__cvta_generic_to_shared(p);
}
__device__ __forceinline__ void ldsm4(uint32_t (&r)[4], uint32_t a) {
    asm volatile("ldmatrix.sync.aligned.m8n8.x4.shared.b16 {%0,%1,%2,%3}, [%4];"
        : "=r"(r[0]), "=r"(r[1]), "=r"(r[2]), "=r"(r[3]) : "r"(a));
}
__device__ __forceinline__ void ldsm2(uint32_t (&r)[2], uint32_t a) {
    asm volatile("ldmatrix.sync.aligned.m8n8.x2.shared.b16 {%0,%1}, [%2];"
        : "=r"(r[0]), "=r"(r[1]) : "r"(a));
}

#define PITCH 36   // floats; rows stride 144B -> 16B aligned, ldmatrix conflict-free
#define NSTG 3     // pipeline stages

// warp-level tf32 mma over one BK=32 stage; fragments via ldmatrix.
template<int MSUB, int NSUB>
__device__ __forceinline__ void warp_mma(
    const float* __restrict__ As, const float* __restrict__ Bs,
    int mrow0, int ncol0, float (&acc)[MSUB][NSUB][4],
    int rA, int cA, int rB, int cB)
{
#pragma unroll
    for (int k8 = 0; k8 < 4; k8++) {
        uint32_t a[MSUB][4];
#pragma unroll
        for (int mi = 0; mi < MSUB; mi++)
            ldsm4(a[mi], s2u(As + (mrow0 + mi*16 + rA)*PITCH + k8*8 + cA));
        uint32_t b[NSUB][2];
#pragma unroll
        for (int ni = 0; ni < NSUB; ni++)
            ldsm2(b[ni], s2u(Bs + (ncol0 + ni*8 + rB)*PITCH + k8*8 + cB));
#pragma unroll
        for (int mi = 0; mi < MSUB; mi++)
#pragma unroll
            for (int ni = 0; ni < NSUB; ni++) {
                asm volatile(
                    "mma.sync.aligned.m16n8k8.row.col.f32.tf32.tf32.f32 "
                    "{%0,%1,%2,%3}, {%4,%5,%6,%7}, {%8,%9}, {%0,%1,%2,%3};"
                    : "+f"(acc[mi][ni][0]), "+f"(acc[mi][ni][1]),
                      "+f"(acc[mi][ni][2]), "+f"(acc[mi][ni][3])
                    : "r"(a[mi][0]), "r"(a[mi][1]), "r"(a[mi][2]), "r"(a[mi][3]),
                      "r"(b[ni][0]), "r"(b[ni][1]));
            }
    }
}

// output layouts
#define LAY_FLAT 0
#define LAY_HEAD 1
#define LAY_QCAT 2
#define LAY_KCAT 3

__device__ __forceinline__ float* out_addr_rt(int lay, float* C, int mrow, int ncol) {
    if (lay == LAY_FLAT) return C + (size_t)mrow*1024 + ncol;
    int b = mrow >> 10, l = mrow & 1023;
    if (lay == LAY_HEAD) {
        int h = ncol >> 6, hd = ncol & 63;
        return C + ((size_t)((b*16 + h)*1024 + l))*64 + hd;
    }
    if (lay == LAY_QCAT) {
        int seg = ncol >> 10, nn = ncol & 1023;
        int h = nn >> 6, hd = nn & 63;
        return C + ((size_t)((b*16 + h)*1024 + l))*192 + seg*64 + hd;
    }
    int h = ncol >> 6, hd = ncol & 63;
    return C + ((size_t)((b*16 + h)*1024 + l))*192 + hd;
}

// ============================================================
// mma_proj: ALL THREE projection GEMMs in one launch.
// grid (40, 32): nb<24 -> Qcat (N=3072), nb<32 -> Kcat, else V (head-major)
// 128x128 block, BK=32, 8 warps, 3-stage cp.async pipeline
// ============================================================
struct ProjArgs {
    const float* Aq; const float* Ak; const float* Av;
    const float* Wq; const float* Wk; const float* Wv;
    const float* bq; const float* bk; const float* bv;
    float* Cq; float* Ck; float* Cv;
};

__global__ void __launch_bounds__(256, 2) mma_proj(ProjArgs p)
{
    extern __shared__ float sm[];
    float* Asb[NSTG]; float* Bsb[NSTG];
#pragma unroll
    for (int s = 0; s < NSTG; s++) {
        Asb[s] = sm + s*2*128*PITCH;
        Bsb[s] = sm + s*2*128*PITCH + 128*PITCH;
    }
    const int tid = threadIdx.x, lane = tid & 31, wid = tid >> 5;
    const int wm = wid & 1, wn = wid >> 1;
    const int g = lane >> 2, t = lane & 3;
    const int rA = ((lane >> 3) & 1)*8 + (lane & 7), cA = (lane >> 4)*4;
    const int rB = lane & 7, cB = ((lane >> 3) & 1)*4;
    const int nb = blockIdx.x, m0 = blockIdx.y * 128;

    const float *A, *BT, *bias; float* C; int n0, lay;
    if (nb < 24)      { A = p.Aq; BT = p.Wq; bias = p.bq; C = p.Cq; n0 = nb*128;      lay = LAY_QCAT; }
    else if (nb < 32) { A = p.Ak; BT = p.Wk; bias = p.bk; C = p.Ck; n0 = (nb-24)*128; lay = LAY_KCAT; }
    else              { A = p.Av; BT = p.Wv; bias = p.bv; C = p.Cv; n0 = (nb-32)*128; lay = LAY_HEAD; }

    float acc[4][4][4] = {};

#define LOAD_STAGE(i) do {                                                 \
        if ((i) < 32) {                                                    \
            int k0 = (i) * 32; int ss = (i) % NSTG;                        \
            _Pragma("unroll")                                              \
            for (int it = 0; it < 4; it++) {                               \
                int j = it*256 + tid;                                      \
                int r = j >> 3, c = j & 7;                                 \
                cpa16(s2u(Asb[ss] + r*PITCH + c*4), A  + (size_t)(m0+r)*1024 + k0 + c*4); \
                cpa16(s2u(Bsb[ss] + r*PITCH + c*4), BT + (size_t)(n0+r)*1024 + k0 + c*4); \
            }                                                              \
        }                                                                  \
        asm volatile("cp.async.commit_group;" ::: "memory");               \
    } while (0)

    LOAD_STAGE(0);
    LOAD_STAGE(1);
    for (int i = 0; i < 32; i++) {
        int s = i % NSTG;
        asm volatile("cp.async.wait_group 1;" ::: "memory");
        __syncthreads();
        LOAD_STAGE(i + 2);
        warp_mma<4,4>(Asb[s], Bsb[s], wm*64, wn*32, acc, rA, cA, rB, cB);
    }
#undef LOAD_STAGE

#pragma unroll
    for (int mi = 0; mi < 4; mi++)
#pragma unroll
        for (int ni = 0; ni < 4; ni++) {
            int mrow = m0 + wm*64 + mi*16 + g;
            int ncol = n0 + wn*32 + ni*8 + t*2;
            float b0 = bias[ncol], b1 = bias[ncol+1];
            float v00 = rnd_tf32(acc[mi][ni][0] + b0), v01 = rnd_tf32(acc[mi][ni][1] + b1);
            float v10 = rnd_tf32(acc[mi][ni][2] + b0), v11 = rnd_tf32(acc[mi][ni][3] + b1);
            *(float2*)out_addr_rt(lay, C, mrow,     ncol) = make_float2(v00, v01);
            *(float2*)out_addr_rt(lay, C, mrow + 8, ncol) = make_float2(v10, v11);
        }
}

// ============================================================
// mma_out: out = ctx @ WoT^T + bias (flat layout, no rounding)
// ============================================================
__global__ void __launch_bounds__(256, 2) mma_out(
    const float* __restrict__ A, const float* __restrict__ BT,
    const float* __restrict__ bias, float* __restrict__ C)
{
    extern __shared__ float sm[];
    float* Asb[NSTG]; float* Bsb[NSTG];
#pragma unroll
    for (int s = 0; s < NSTG; s++) {
        Asb[s] = sm + s*2*128*PITCH;
        Bsb[s] = sm + s*2*128*PITCH + 128*PITCH;
    }
    const int tid = threadIdx.x, lane = tid & 31, wid = tid >> 5;
    const int wm = wid & 1, wn = wid >> 1;
    const int g = lane >> 2, t = lane & 3;
    const int rA = ((lane >> 3) & 1)*8 + (lane & 7), cA = (lane >> 4)*4;
    const int rB = lane & 7, cB = ((lane >> 3) & 1)*4;
    const int m0 = blockIdx.y * 128, n0 = blockIdx.x * 128;

    float acc[4][4][4] = {};

#define LOAD_STAGE(i) do {                                                 \
        if ((i) < 32) {                                                    \
            int k0 = (i) * 32; int ss = (i) % NSTG;                        \
            _Pragma("unroll")                                              \
            for (int it = 0; it < 4; it++) {                               \
                int j = it*256 + tid;                                      \
                int r = j >> 3, c = j & 7;                                 \
                cpa16(s2u(Asb[ss] + r*PITCH + c*4), A  + (size_t)(m0+r)*1024 + k0 + c*4); \
                cpa16(s2u(Bsb[ss] + r*PITCH + c*4), BT + (size_t)(n0+r)*1024 + k0 + c*4); \
            }                                                              \
        }                                                                  \
        asm volatile("cp.async.commit_group;" ::: "memory");               \
    } while (0)

    LOAD_STAGE(0);
    LOAD_STAGE(1);
    for (int i = 0; i < 32; i++) {
        int s = i % NSTG;
        asm volatile("cp.async.wait_group 1;" ::: "memory");
        __syncthreads();
        LOAD_STAGE(i + 2);
        warp_mma<4,4>(Asb[s], Bsb[s], wm*64, wn*32, acc, rA, cA, rB, cB);
    }
#undef LOAD_STAGE

#pragma unroll
    for (int mi = 0; mi < 4; mi++)
#pragma unroll
        for (int ni = 0; ni < 4; ni++) {
            int mrow = m0 + wm*64 + mi*16 + g;
            int ncol = n0 + wn*32 + ni*8 + t*2;
            float b0 = bias[ncol], b1 = bias[ncol+1];
            *(float2*)(C + (size_t)mrow*1024 + ncol) =
                make_float2(acc[mi][ni][0] + b0, acc[mi][ni][1] + b1);
            *(float2*)(C + (size_t)(mrow+8)*1024 + ncol) =
                make_float2(acc[mi][ni][2] + b0, acc[mi][ni][3] + b1);
        }
}

// ============================================================
// mma_score: raw scaled scores + per-tile row partials, K=192
// ============================================================
__global__ void __launch_bounds__(256, 2) mma_score(
    const float* __restrict__ qcat, const float* __restrict__ kcat,
    float* __restrict__ attn, float* __restrict__ pmax, float* __restrict__ psum)
{
    extern __shared__ float sm[];
    float* Asb[NSTG]; float* Bsb[NSTG];
#pragma unroll
    for (int s = 0; s < NSTG; s++) {
        Asb[s] = sm + s*2*128*PITCH;
        Bsb[s] = sm + s*2*128*PITCH + 128*PITCH;
    }
    const int tid = threadIdx.x, lane = tid & 31, wid = tid >> 5;
    const int wm = wid & 1, wn = wid >> 1;
    const int g = lane >> 2, t = lane & 3;
    const int rA = ((lane >> 3) & 1)*8 + (lane & 7), cA = (lane >> 4)*4;
    const int rB = lane & 7, cB = ((lane >> 3) & 1)*4;
    const int bh = blockIdx.z;
    const int q0 = blockIdx.y * 128, n0 = blockIdx.x * 128;
    const float* Ab = qcat + (size_t)bh*NL*192 + (size_t)q0*192;
    const float* Bb = kcat + (size_t)bh*NL*192 + (size_t)n0*192;

    float acc[4][4][4] = {};

#define LOAD_STAGE_S(i) do {                                               \
        if ((i) < 6) {                                                     \
            int k0 = (i) * 32; int ss = (i) % NSTG;                        \
            _Pragma("unroll")                                              \
            for (int it = 0; it < 4; it++) {                               \
                int j = it*256 + tid;                                      \
                int r = j >> 3, c = j & 7;                                 \
                cpa16(s2u(Asb[ss] + r*PITCH + c*4), Ab + (size_t)r*192 + k0 + c*4); \
                cpa16(s2u(Bsb[ss] + r*PITCH + c*4), Bb + (size_t)r*192 + k0 + c*4); \
            }                                                              \
        }                                                                  \
        asm volatile("cp.async.commit_group;" ::: "memory");               \
    } while (0)

    LOAD_STAGE_S(0);
    LOAD_STAGE_S(1);
    for (int i = 0; i < 6; i++) {
        int s = i % NSTG;
        asm volatile("cp.async.wait_group 1;" ::: "memory");
        __syncthreads();
        LOAD_STAGE_S(i + 2);
        warp_mma<4,4>(Asb[s], Bsb[s], wm*64, wn*32, acc, rA, cA, rB, cB);
    }
#undef LOAD_STAGE_S

    const float sc = 1.0f / 24.0f;
#pragma unroll
    for (int mi = 0; mi < 4; mi++)
#pragma unroll
        for (int ni = 0; ni < 4; ni++) {
            int mrow = q0 + wm*64 + mi*16 + g;
            int ncol = n0 + wn*32 + ni*8 + t*2;
            float* d0 = attn + ((size_t)bh*NL + mrow)*NL + ncol;
            float* d1 = attn + ((size_t)bh*NL + mrow + 8)*NL + ncol;
            *(float2*)d0 = make_float2(acc[mi][ni][0]*sc, acc[mi][ni][1]*sc);
            *(float2*)d1 = make_float2(acc[mi][ni][2]*sc, acc[mi][ni][3]*sc);
        }

    __syncthreads();
    float* pm = sm;          // [128][4]
    float* ps = sm + 512;    // [128][4]
#pragma unroll
    for (int mi = 0; mi < 4; mi++)
#pragma unroll
        for (int half = 0; half < 2; half++) {
            float v[8];
#pragma unroll
            for (int ni = 0; ni < 4; ni++) {
                v[ni*2+0] = acc[mi][ni][half*2+0] * sc;
                v[ni*2+1] = acc[mi][ni][half*2+1] * sc;
            }
            float mx = v[0];
#pragma unroll
            for (int q = 1; q < 8; q++) mx = fmaxf(mx, v[q]);
            mx = fmaxf(mx, __shfl_xor_sync(0xffffffffu, mx, 1));
            mx = fmaxf(mx, __shfl_xor_sync(0xffffffffu, mx, 2));
            float se = 0.f;
#pragma unroll
            for (int q = 0; q < 8; q++) se += __expf(v[q] - mx);
            se += __shfl_xor_sync(0xffffffffu, se, 1);
            se += __shfl_xor_sync(0xffffffffu, se, 2);
            if (t == 0) {
                int lr = wm*64 + mi*16 + half*8 + g;
                pm[lr*4 + wn] = mx;
                ps[lr*4 + wn] = se;
            }
        }
    __syncthreads();
    if (tid < 128) {
        int lr = tid;
        float M = pm[lr*4];
#pragma unroll
        for (int q = 1; q < 4; q++) M = fmaxf(M, pm[lr*4+q]);
        float S = 0.f;
#pragma unroll
        for (int q = 0; q < 4; q++) S += ps[lr*4+q] * __expf(pm[lr*4+q] - M);
        size_t row = (size_t)bh*NL + q0 + lr;
        pmax[row*8 + blockIdx.x] = M;
        psum[row*8 + blockIdx.x] = S;
    }
}

// ============================================================
// combine_rows
// ============================================================
__global__ void __launch_bounds__(256) combine_rows(
    const float* __restrict__ pmax, const float* __restrict__ psum,
    float* __restrict__ rowm, float* __restrict__ rowi)
{
    int row = blockIdx.x * 256 + threadIdx.x;
    const float* pmr = pmax + (size_t)row*8;
    const float* psr = psum + (size_t)row*8;
    float M = pmr[0];
#pragma unroll
    for (int q = 1; q < 8; q++) M = fmaxf(M, pmr[q]);
    float S = 0.f;
#pragma unroll
    for (int q = 0; q < 8; q++) S += psr[q] * __expf(pmr[q] - M);
    rowm[row] = M;
    rowi[row] = 1.0f / S;
}

// ============================================================
// mma_ctx: fused softmax-apply + PV gemm (in-place attn normalize)
// ============================================================
__global__ void __launch_bounds__(256, 2) mma_ctx(
    float* __restrict__ attn, const float* __restrict__ vt,
    const float* __restrict__ rowm, const float* __restrict__ rowi,
    float* __restrict__ ctx)
{
    extern __shared__ float sm[];
    float* Asb[NSTG]; float* Bsb[NSTG];
#pragma unroll
    for (int s = 0; s < NSTG; s++) {
        Asb[s] = sm + s*(128+64)*PITCH;
        Bsb[s] = sm + s*(128+64)*PITCH + 128*PITCH;
    }
    float* rowM = sm + NSTG*(128+64)*PITCH;
    float* rowI = rowM + 128;
    const int tid = threadIdx.x, lane = tid & 31, wid = tid >> 5;
    const int wm = wid & 1, wn = wid >> 1;
    const int g = lane >> 2, t = lane & 3;
    const int rA = ((lane >> 3) & 1)*8 + (lane & 7), cA = (lane >> 4)*4;
    const int rB = lane & 7, cB = ((lane >> 3) & 1)*4;
    const int bh = blockIdx.y, q0 = blockIdx.x * 128;
    float* Ab = attn + (size_t)bh*NL*NL + (size_t)q0*NL;
    const float* Bb = vt + (size_t)bh*64*NL;

    if (tid < 128) {
        rowM[tid] = rowm[(size_t)bh*NL + q0 + tid];
        rowI[tid] = rowi[(size_t)bh*NL + q0 + tid];
    }

    float acc[4][2][4] = {};

#define LOAD_STAGE_C(i) do {                                               \
        if ((i) < 32) {                                                    \
            int k0 = (i) * 32; int ss = (i) % NSTG;                        \
            _Pragma("unroll")                                              \
            for (int it = 0; it < 4; it++) {                               \
                int j = it*256 + tid;                                      \
                int r = j >> 3, c = j & 7;                                 \
                cpa16(s2u(Asb[ss] + r*PITCH + c*4), Ab + (size_t)r*NL + k0 + c*4); \
            }                                                              \
            _Pragma("unroll")                                              \
            for (int it = 0; it < 2; it++) {                               \
                int j = it*256 + tid;                                      \
                int r = j >> 3, c = j & 7;                                 \
                cpa16(s2u(Bsb[ss] + r*PITCH + c*4), Bb + (size_t)r*NL + k0 + c*4); \
            }                                                              \
        }                                                                  \
        asm volatile("cp.async.commit_group;" ::: "memory");               \
    } while (0)

    LOAD_STAGE_C(0);
    LOAD_STAGE_C(1);
    for (int i = 0; i < 32; i++) {
        int s = i % NSTG;
        asm volatile("cp.async.wait_group 1;" ::: "memory");
        __syncthreads();
        LOAD_STAGE_C(i + 2);
        {
            int k0 = i * 32;
#pragma unroll
            for (int it = 0; it < 4; it++) {
                int j = it*256 + tid;
                int r = j >> 3, c4 = j & 7;
                float4* ap = (float4*)(Asb[s] + r*PITCH + c4*4);
                float4 v = *ap;
                float M = rowM[r], I = rowI[r];
                v.x = rnd_tf32(__expf(v.x - M) * I);
                v.y = rnd_tf32(__expf(v.y - M) * I);
                v.z = rnd_tf32(__expf(v.z - M) * I);
                v.w = rnd_tf32(__expf(v.w - M) * I);
                *ap = v;
                *(float4*)(Ab + (size_t)r*NL + k0 + c4*4) = v;
            }
        }
        __syncthreads();
        warp_mma<4,2>(Asb[s], Bsb[s], wm*64, wn*16, acc, rA, cA, rB, cB);
    }
#undef LOAD_STAGE_C

    const int b = bh >> 4, hh = bh & 15;
#pragma unroll
    for (int mi = 0; mi < 4; mi++)
#pragma unroll
        for (int ni = 0; ni < 2; ni++) {
            int mrow = q0 + wm*64 + mi*16 + g;
            int ncol = wn*16 + ni*8 + t*2;
            float v00 = rnd_tf32(acc[mi][ni][0]), v01 = rnd_tf32(acc[mi][ni][1]);
            float v10 = rnd_tf32(acc[mi][ni][2]), v11 = rnd_tf32(acc[mi][ni][3]);
            *(float2*)(ctx + ((size_t)(b*1024 + mrow))*1024 + hh*64 + ncol) = make_float2(v00, v01);
            *(float2*)(ctx + ((size_t)(b*1024 + mrow + 8))*1024 + hh*64 + ncol) = make_float2(v10, v11);
        }
}

// ============================================================
// batched 1024x1024 transpose (+ tf32 round), 6 matrices in one launch
// ============================================================
struct TP6 { const float* src[6]; float* dst[6]; };

__global__ void __launch_bounds__(256) transpose6(TP6 p)
{
    __shared__ float tbuf[32][33];
    const int z = blockIdx.z;
    const float* src = p.src[z];
    float* dst = p.dst[z];
    const int bx = blockIdx.x * 32, by = blockIdx.y * 32;
    const int x = threadIdx.x, y0 = threadIdx.y;
#pragma unroll
    for (int dy = 0; dy < 32; dy += 8)
        tbuf[y0+dy][x] = src[(size_t)(by + y0 + dy)*1024 + bx + x];
    __syncthreads();
#pragma unroll
    for (int dy = 0; dy < 32; dy += 8)
        dst[(size_t)(bx + y0 + dy)*1024 + by + x] = rnd_tf32(tbuf[x][y0+dy]);
}

// v transpose: vt[bh][hd][l] = v[bh][l][hd] (+round)
__global__ void __launch_bounds__(256) transpose_v(
    const float* __restrict__ src, float* __restrict__ dst)
{
    __shared__ float tbuf[32][33];
    const int bx = blockIdx.x * 32, by = blockIdx.y * 32;
    const size_t base = (size_t)blockIdx.z * NL * 64;
    const int x = threadIdx.x, y0 = threadIdx.y;
#pragma unroll
    for (int dy = 0; dy < 32; dy += 8)
        tbuf[y0+dy][x] = src[base + (size_t)(by + y0 + dy)*64 + bx + x];
    __syncthreads();
#pragma unroll
    for (int dy = 0; dy < 32; dy += 8)
        dst[base + (size_t)(bx + y0 + dy)*NL + by + x] = rnd_tf32(tbuf[x][y0+dy]);
}

// round q,k,v into tf32-exact copies (one launch)
__global__ void __launch_bounds__(256) round3(
    const float4* __restrict__ q, const float4* __restrict__ k,
    const float4* __restrict__ v, float4* __restrict__ qr,
    float4* __restrict__ kr, float4* __restrict__ vr)
{
    int i = blockIdx.x * 256 + threadIdx.x;      // 0 .. 3*1048576-1
    int seg = i >> 20, j = i & 1048575;
    const float4* in = (seg == 0) ? q : (seg == 1) ? k : v;
    float4* out = (seg == 0) ? qr : (seg == 1) ? kr : vr;
    float4 x = in[j];
    x.x = rnd_tf32(x.x); x.y = rnd_tf32(x.y);
    x.z = rnd_tf32(x.z); x.w = rnd_tf32(x.w);
    out[j] = x;
}

__global__ void __launch_bounds__(256) concat_bias(
    const float* __restrict__ a, const float* __restrict__ b,
    const float* __restrict__ c, float* __restrict__ o)
{
    int i = blockIdx.x * 256 + threadIdx.x;
    o[i] = (i < 1024) ? a[i] : (i < 2048) ? b[i - 1024] : c[i - 2048];
}

// ============================================================
// chord/bass features -> Kcat segments 1,2 (replicated over b)
// ============================================================
__global__ __launch_bounds__(256) void chordfeat(
    const int* __restrict__ pc, const int* __restrict__ bon,
    const float* __restrict__ Wc, const float* __restrict__ bc,
    const float* __restrict__ Wb, const float* __restrict__ bb,
    float* __restrict__ kcat)
{
    int idx = blockIdx.x * 256 + threadIdx.x;
    int l = idx >> 10, n = idx & 1023;
    float sc = bc[n], sb = bb[n];
#pragma unroll
    for (int p = 0; p < 12; p++) {
        sc += (float)pc[l*12 + p] * Wc[p*1024 + n];
        sb += (float)bon[l*12 + p] * Wb[p*1024 + n];
    }
    sc = rnd_tf32(sc); sb = rnd_tf32(sb);
    int h = n >> 6, hd = n & 63;
#pragma unroll
    for (int b = 0; b < 4; b++) {
        size_t row = ((size_t)((b*16 + h)*1024 + l))*192;
        kcat[row + 64 + hd]  = sc;
        kcat[row + 128 + hd] = sb;
    }
}

// ============================================================
// launch
// ============================================================
extern "C" void kernel_launch(void* const* d_in, const int* in_sizes, int n_in,
                              void* d_out, int out_size)
{
    const float* query = (const float*)d_in[0];
    const float* key   = (const float*)d_in[1];
    const float* value = (const float*)d_in[2];
    const int*   pc    = (const int*)d_in[3];
    const int*   bon   = (const int*)d_in[4];
    const float* Wpq = (const float*)d_in[5],  *bpq = (const float*)d_in[6];
    const float* Whq = (const float*)d_in[7],  *bhq = (const float*)d_in[8];
    const float* Wvq = (const float*)d_in[9],  *bvq = (const float*)d_in[10];
    const float* Wk  = (const float*)d_in[11], *bk  = (const float*)d_in[12];
    const float* Wv  = (const float*)d_in[13], *bv  = (const float*)d_in[14];
    const float* Wc  = (const float*)d_in[15], *bc  = (const float*)d_in[16];
    const float* Wb  = (const float*)d_in[17], *bb  = (const float*)d_in[18];
    const float* Wo  = (const float*)d_in[19], *bo  = (const float*)d_in[20];

    float *qcat_p, *kcat_p, *v_p, *vt_p, *ctx_p, *wt_p, *bcat_p;
    float *qr_p, *kr_p, *vr_p, *pmax_p, *psum_p, *rowm_p, *rowi_p;
    cudaGetSymbolAddress((void**)&qcat_p, g_qcat);
    cudaGetSymbolAddress((void**)&kcat_p, g_kcat);
    cudaGetSymbolAddress((void**)&v_p,    g_v);
    cudaGetSymbolAddress((void**)&vt_p,   g_vt);
    cudaGetSymbolAddress((void**)&ctx_p,  g_ctx);
    cudaGetSymbolAddress((void**)&wt_p,   g_wt);
    cudaGetSymbolAddress((void**)&bcat_p, g_bcat);
    cudaGetSymbolAddress((void**)&qr_p,   g_qr);
    cudaGetSymbolAddress((void**)&kr_p,   g_kr);
    cudaGetSymbolAddress((void**)&vr_p,   g_vr);
    cudaGetSymbolAddress((void**)&pmax_p, g_pmax);
    cudaGetSymbolAddress((void**)&psum_p, g_psum);
    cudaGetSymbolAddress((void**)&rowm_p, g_rowm);
    cudaGetSymbolAddress((void**)&rowi_p, g_rowi);

    float* WqcatT = wt_p;                       // [3072 x 1024]
    float* WkT    = wt_p + 3u*1024u*1024u;
    float* WvT    = wt_p + 4u*1024u*1024u;
    float* WoT    = wt_p + 5u*1024u*1024u;

    float* out  = (float*)d_out;
    float* attn = out + (size_t)NB * NL * ND;

    const int SM_BIG = NSTG * 2 * 128 * PITCH * 4;                  // 110592
    const int SM_CTX = (NSTG * (128+64) * PITCH + 256) * 4;         // 83968
    cudaFuncSetAttribute(mma_proj,  cudaFuncAttributeMaxDynamicSharedMemorySize, SM_BIG);
    cudaFuncSetAttribute(mma_out,   cudaFuncAttributeMaxDynamicSharedMemorySize, SM_BIG);
    cudaFuncSetAttribute(mma_score, cudaFuncAttributeMaxDynamicSharedMemorySize, SM_BIG);
    cudaFuncSetAttribute(mma_ctx,   cudaFuncAttributeMaxDynamicSharedMemorySize, SM_CTX);

    // prologue: round inputs, transpose+round weights, concat bias
    round3<<<12288, 256>>>((const float4*)query, (const float4*)key, (const float4*)value,
                           (float4*)qr_p, (float4*)kr_p, (float4*)vr_p);
    TP6 tp;
    tp.src[0] = Wpq; tp.dst[0] = WqcatT + 0u*1024u*1024u;
    tp.src[1] = Whq; tp.dst[1] = WqcatT + 1u*1024u*1024u;
    tp.src[2] = Wvq; tp.dst[2] = WqcatT + 2u*1024u*1024u;
    tp.src[3] = Wk;  tp.dst[3] = WkT;
    tp.src[4] = Wv;  tp.dst[4] = WvT;
    tp.src[5] = Wo;  tp.dst[5] = WoT;
    dim3 tb(32, 8);
    transpose6<<<dim3(32, 32, 6), tb>>>(tp);
    concat_bias<<<12, 256>>>(bpq, bhq, bvq, bcat_p);

    // all projections in one launch
    ProjArgs pa;
    pa.Aq = qr_p; pa.Ak = kr_p; pa.Av = vr_p;
    pa.Wq = WqcatT; pa.Wk = WkT; pa.Wv = WvT;
    pa.bq = bcat_p; pa.bk = bk; pa.bv = bv;
    pa.Cq = qcat_p; pa.Ck = kcat_p; pa.Cv = v_p;
    mma_proj<<<dim3(40, 32), 256, SM_BIG>>>(pa);

    transpose_v<<<dim3(2, 32, NBH), tb>>>(v_p, vt_p);
    chordfeat<<<4096, 256>>>(pc, bon, Wc, bc, Wb, bb, kcat_p);

    mma_score<<<dim3(8, 8, NBH), 256, SM_BIG>>>(qcat_p, kcat_p, attn, pmax_p, psum_p);
    combine_rows<<<NBH*NL/256, 256>>>(pmax_p, psum_p, rowm_p, rowi_p);
    mma_ctx<<<dim3(8, NBH), 256, SM_CTX>>>(attn, vt_p, rowm_p, rowi_p, ctx_p);
    mma_out<<<dim3(8, 32), 256, SM_BIG>>>(ctx_p, WoT, bo, out);
}